// round 9
// baseline (speedup 1.0000x reference)
#include <cuda_runtime.h>
#include <cuda_bf16.h>
#include <cstdint>

#define N_NODES 50000
#define N_EDGES 600000
#define D 128
#define DE 32

// ---------------------------------------------------------------------------
// Scratch (static device globals — no runtime allocation allowed)
// ---------------------------------------------------------------------------
__device__ int   g_src[N_EDGES];
__device__ int   g_dst[N_EDGES];
__device__ float g_bufA[N_NODES * D];
__device__ float g_bufB[N_NODES * D];
__device__ float g_bufC[N_NODES * D];
__device__ int   g_is64;
// node-GEMM weights: [6][128x128 bf16] in B-operand layout (stride 256B, XOR swizzle)
__device__ __nv_bfloat16 g_whi[6][D * D];
__device__ __nv_bfloat16 g_wlo[6][D * D];
// edge weights: [2 layers][128 n-rows x 80B stride] hi/lo planes (10240 B each)
__device__ __nv_bfloat16 g_wehi[2][5120];
__device__ __nv_bfloat16 g_welo[2][5120];

// ---------------------------------------------------------------------------
// helpers
// ---------------------------------------------------------------------------
__device__ __forceinline__ uint32_t smem_to_u32(const void* p) {
    uint32_t a;
    asm("{ .reg .u64 t; cvta.to.shared.u64 t, %1; cvt.u32.u64 %0, t; }" : "=r"(a) : "l"(p));
    return a;
}

// node-GEMM plane: [128 rows x 128 cols] bf16, row stride 256B, 16B chunks
// XOR-swizzled by (row & 7)
__device__ __host__ __forceinline__ uint32_t sw_off(int row, int col) {
    return (uint32_t)row * 256u + (uint32_t)(((col >> 3) ^ (row & 7)) << 4)
         + (uint32_t)(col & 7) * 2u;
}
// edge plane: [rows x 32 cols] bf16, row stride 80B (80 mod 128 pattern makes
// 8 consecutive rows hit distinct 16B banks -> ldmatrix conflict-free, no XOR)
__device__ __host__ __forceinline__ uint32_t esw_off(int row, int col) {
    return (uint32_t)row * 80u + (uint32_t)((col >> 3) << 4) + (uint32_t)(col & 7) * 2u;
}

__device__ __forceinline__ void ldsm4(uint32_t* r, uint32_t addr) {
    asm volatile("ldmatrix.sync.aligned.m8n8.x4.shared.b16 {%0,%1,%2,%3}, [%4];"
                 : "=r"(r[0]), "=r"(r[1]), "=r"(r[2]), "=r"(r[3]) : "r"(addr));
}

__device__ __forceinline__ void mma_bf16(float* d, const uint32_t* a, const uint32_t* b) {
    asm volatile("mma.sync.aligned.m16n8k16.row.col.f32.bf16.bf16.f32 "
                 "{%0,%1,%2,%3}, {%4,%5,%6,%7}, {%8,%9}, {%0,%1,%2,%3};"
                 : "+f"(d[0]), "+f"(d[1]), "+f"(d[2]), "+f"(d[3])
                 : "r"(a[0]), "r"(a[1]), "r"(a[2]), "r"(a[3]), "r"(b[0]), "r"(b[1]));
}

__device__ __forceinline__ void split_pack(float4 v, uint2& hi, uint2& lo) {
    __nv_bfloat16 hx = __float2bfloat16(v.x), hy = __float2bfloat16(v.y);
    __nv_bfloat16 hz = __float2bfloat16(v.z), hw = __float2bfloat16(v.w);
    __nv_bfloat16 lx = __float2bfloat16(v.x - __bfloat162float(hx));
    __nv_bfloat16 ly = __float2bfloat16(v.y - __bfloat162float(hy));
    __nv_bfloat16 lz = __float2bfloat16(v.z - __bfloat162float(hz));
    __nv_bfloat16 lw = __float2bfloat16(v.w - __bfloat162float(hw));
    hi.x = ((uint32_t)__bfloat16_as_ushort(hy) << 16) | __bfloat16_as_ushort(hx);
    hi.y = ((uint32_t)__bfloat16_as_ushort(hw) << 16) | __bfloat16_as_ushort(hz);
    lo.x = ((uint32_t)__bfloat16_as_ushort(ly) << 16) | __bfloat16_as_ushort(lx);
    lo.y = ((uint32_t)__bfloat16_as_ushort(lw) << 16) | __bfloat16_as_ushort(lz);
}

// ---------------------------------------------------------------------------
// edge_index dtype detection / conversion / copy
// ---------------------------------------------------------------------------
__global__ void detect_kernel(const int* __restrict__ p, int n_words) {
    if (threadIdx.x == 0 && blockIdx.x == 0) {
        int all0 = 1;
        int lim = n_words / 2 < 64 ? n_words / 2 : 64;
        for (int i = 0; i < lim; i++) {
            if (p[2 * i + 1] != 0) { all0 = 0; break; }
        }
        g_is64 = all0;
    }
}

__global__ void convert_kernel(const void* __restrict__ eidx) {
    int e = blockIdx.x * blockDim.x + threadIdx.x;
    if (e >= N_EDGES) return;
    if (g_is64) {
        const long long* p = (const long long*)eidx;
        g_src[e] = (int)p[e];
        g_dst[e] = (int)p[N_EDGES + e];
    } else {
        const int* p = (const int*)eidx;
        g_src[e] = p[e];
        g_dst[e] = p[N_EDGES + e];
    }
}

__global__ void copy_kernel(const float4* __restrict__ src, float4* __restrict__ dst, int n4) {
    int i = blockIdx.x * blockDim.x + threadIdx.x;
    if (i < n4) dst[i] = src[i];
}

// ---------------------------------------------------------------------------
// Weight pre-splits
// ---------------------------------------------------------------------------
__global__ void wsplit_kernel(const float* __restrict__ W,
                              __nv_bfloat16* __restrict__ whi,
                              __nv_bfloat16* __restrict__ wlo) {
    int idx = blockIdx.x * blockDim.x + threadIdx.x;
    if (idx >= D * D) return;
    int n = idx >> 7;
    int k = idx & 127;
    float w = W[k * D + n];
    __nv_bfloat16 hi = __float2bfloat16(w);
    __nv_bfloat16 lo = __float2bfloat16(w - __bfloat162float(hi));
    uint32_t off = sw_off(n, k);
    *(__nv_bfloat16*)((char*)whi + off) = hi;
    *(__nv_bfloat16*)((char*)wlo + off) = lo;
}

// we[32][128] -> B-operand edge layout: row n (0..127), col k (0..31)
__global__ void wesplit_kernel(const float* __restrict__ we,
                               __nv_bfloat16* __restrict__ whi,
                               __nv_bfloat16* __restrict__ wlo) {
    int idx = blockIdx.x * blockDim.x + threadIdx.x;   // 4096
    if (idx >= DE * D) return;
    int n = idx & 127;
    int k = idx >> 7;
    float w = we[k * D + n];
    __nv_bfloat16 hi = __float2bfloat16(w);
    __nv_bfloat16 lo = __float2bfloat16(w - __bfloat162float(hi));
    uint32_t off = esw_off(n, k);
    *(__nv_bfloat16*)((char*)whi + off) = hi;
    *(__nv_bfloat16*)((char*)wlo + off) = lo;
}

// ---------------------------------------------------------------------------
// HMMA edge kernel: tile = 128 edges per CTA (256 thr / 8 warps).
//   emb[128,128] = ea_tile[128,32] @ we[32,128] + be   (bf16 hi/lo, 3 terms)
//   msg = relu(emb + X[src]);  agg[dst] += msg  (red.v4, coalesced per warp)
// smem: A hi/lo (2x10240) + B hi/lo (2x10240) + emb 128x132 f32 (67584)
// ---------------------------------------------------------------------------
static constexpr int EOFF_AHI = 0;
static constexpr int EOFF_ALO = 10240;
static constexpr int EOFF_BHI = 20480;
static constexpr int EOFF_BLO = 30720;
static constexpr int EOFF_EMB = 40960;
static constexpr int EMB_STRIDE = 132;           // floats; 528B, conflict-free
static constexpr int SMEM_EDGE = 40960 + 128 * EMB_STRIDE * 4;   // 108544

__global__ void __launch_bounds__(256) edge_mma(
    const float* __restrict__ X, const float* __restrict__ ea,
    const __nv_bfloat16* __restrict__ wehi, const __nv_bfloat16* __restrict__ welo,
    const float* __restrict__ be, float* __restrict__ agg)
{
    extern __shared__ char sm[];
    uint32_t smem_base = smem_to_u32(sm);
    int tid  = threadIdx.x;
    int lane = tid & 31;
    int wid  = tid >> 5;
    int e0   = blockIdx.x * 128;

    // stage B planes (pre-split, linear copy)
    {
        const uint4* hg = (const uint4*)wehi;
        const uint4* lg = (const uint4*)welo;
        uint4* hs = (uint4*)(sm + EOFF_BHI);
        uint4* ls = (uint4*)(sm + EOFF_BLO);
        for (int i = tid; i < 640; i += 256) { hs[i] = hg[i]; ls[i] = lg[i]; }
    }

    // stage ea tile: 128 edges x 32 attrs = 1024 float4, split hi/lo
    #pragma unroll
    for (int j = 0; j < 4; j++) {
        int idx = tid + j * 256;
        int row = idx >> 3;                   // edge within tile
        int c4  = idx & 7;                    // float4 within row
        int e   = e0 + row;
        if (e >= N_EDGES) e = N_EDGES - 1;
        float4 v = ((const float4*)ea)[(size_t)e * 8 + c4];
        uint2 hi, lo;
        split_pack(v, hi, lo);
        uint32_t off = (uint32_t)row * 80u + (uint32_t)(c4 >> 1) * 16u + (uint32_t)(c4 & 1) * 8u;
        *(uint2*)(sm + EOFF_AHI + off) = hi;
        *(uint2*)(sm + EOFF_ALO + off) = lo;
    }
    __syncthreads();

    // accumulators with bias folded in
    float acc[16][4];
    #pragma unroll
    for (int nt = 0; nt < 16; nt++) {
        float2 bv = *(const float2*)(be + nt * 8 + (lane & 3) * 2);
        acc[nt][0] = bv.x; acc[nt][1] = bv.y;
        acc[nt][2] = bv.x; acc[nt][3] = bv.y;
    }

    int am = lane >> 3;
    int arow = wid * 16 + (lane & 7) + (am & 1) * 8;
    int achunkoff = am >> 1;
    int brow_loc  = ((lane >> 4) << 3) + (lane & 7);
    int bchunkoff = (lane >> 3) & 1;

    uint32_t aHi = smem_base + EOFF_AHI, aLo = smem_base + EOFF_ALO;
    uint32_t bHi = smem_base + EOFF_BHI, bLo = smem_base + EOFF_BLO;

    #pragma unroll
    for (int ks = 0; ks < 2; ks++) {
        uint32_t ah[4], al[4];
        uint32_t aoff = (uint32_t)arow * 80u + (uint32_t)(ks * 2 + achunkoff) * 16u;
        ldsm4(ah, aHi + aoff);
        ldsm4(al, aLo + aoff);
        #pragma unroll
        for (int np = 0; np < 8; np++) {
            uint32_t boff = (uint32_t)(np * 16 + brow_loc) * 80u
                          + (uint32_t)(ks * 2 + bchunkoff) * 16u;
            uint32_t bh[4], bl[4];
            ldsm4(bh, bHi + boff);
            ldsm4(bl, bLo + boff);
            mma_bf16(acc[2 * np + 0], ah, bh + 0);
            mma_bf16(acc[2 * np + 1], ah, bh + 2);
            mma_bf16(acc[2 * np + 0], ah, bl + 0);
            mma_bf16(acc[2 * np + 1], ah, bl + 2);
            mma_bf16(acc[2 * np + 0], al, bh + 0);
            mma_bf16(acc[2 * np + 1], al, bh + 2);
        }
    }

    // write emb to smem (padded rows -> conflict-free float2 stores)
    {
        int r0 = wid * 16 + (lane >> 2);
        int r1 = r0 + 8;
        int cb = (lane & 3) * 2;
        float* embp = (float*)(sm + EOFF_EMB);
        #pragma unroll
        for (int nt = 0; nt < 16; nt++) {
            *(float2*)(embp + r0 * EMB_STRIDE + nt * 8 + cb) = make_float2(acc[nt][0], acc[nt][1]);
            *(float2*)(embp + r1 * EMB_STRIDE + nt * 8 + cb) = make_float2(acc[nt][2], acc[nt][3]);
        }
    }
    __syncthreads();

    // gather + relu + scatter-add (coalesced 128B per warp per edge)
    const float* embp = (const float*)(sm + EOFF_EMB);
    #pragma unroll
    for (int i = 0; i < 16; i++) {
        int er = wid * 16 + i;
        int e  = e0 + er;
        if (e < N_EDGES) {
            int src = g_src[e];
            int dst = g_dst[e];
            float4 xv = ((const float4*)X)[(size_t)src * 32 + lane];
            float4 em = *(const float4*)(embp + er * EMB_STRIDE + lane * 4);
            float mx = fmaxf(em.x + xv.x, 0.f);
            float my = fmaxf(em.y + xv.y, 0.f);
            float mz = fmaxf(em.z + xv.z, 0.f);
            float mw = fmaxf(em.w + xv.w, 0.f);
            float* p = agg + (size_t)dst * D + lane * 4;
            asm volatile("red.global.add.v4.f32 [%0], {%1,%2,%3,%4};"
                         :: "l"(p), "f"(mx), "f"(my), "f"(mz), "f"(mw) : "memory");
        }
    }
}

// ---------------------------------------------------------------------------
// HMMA node GEMM (unchanged from round 7)
// ---------------------------------------------------------------------------
static constexpr int OFF_AHI = 0;
static constexpr int OFF_ALO = 32768;
static constexpr int OFF_BHI = 2 * 32768;
static constexpr int OFF_BLO = 3 * 32768;
static constexpr int SMEM_MMA = 4 * 32768;   // 128 KB

template<bool RELU>
__global__ void __launch_bounds__(256) gemm_mma(
    const float* __restrict__ A,
    const __nv_bfloat16* __restrict__ Whi, const __nv_bfloat16* __restrict__ Wlo,
    const float* __restrict__ b, float* __restrict__ C)
{
    extern __shared__ char sm[];
    uint32_t smem_base = smem_to_u32(sm);
    int tid  = threadIdx.x;
    int lane = tid & 31;
    int wid  = tid >> 5;

    {
        const uint4* hg = (const uint4*)Whi;
        const uint4* lg = (const uint4*)Wlo;
        uint4* hs = (uint4*)(sm + OFF_BHI);
        uint4* ls = (uint4*)(sm + OFF_BLO);
        #pragma unroll
        for (int i = 0; i < 8; i++) {
            hs[tid + i * 256] = hg[tid + i * 256];
            ls[tid + i * 256] = lg[tid + i * 256];
        }
    }

    int row0 = blockIdx.x * 128;
    #pragma unroll
    for (int i = 0; i < 16; i++) {
        int idx = tid + i * 256;
        int row = idx >> 5;
        int c4  = idx & 31;
        int rg  = row0 + row;
        if (rg >= N_NODES) rg = N_NODES - 1;
        float4 v = ((const float4*)A)[(size_t)rg * 32 + c4];
        uint2 hi, lo;
        split_pack(v, hi, lo);
        uint32_t off = sw_off(row, c4 * 4);
        *(uint2*)(sm + OFF_AHI + off) = hi;
        *(uint2*)(sm + OFF_ALO + off) = lo;
    }
    __syncthreads();

    float acc[16][4];
    #pragma unroll
    for (int nt = 0; nt < 16; nt++) {
        float2 bv = *(const float2*)(b + nt * 8 + (lane & 3) * 2);
        acc[nt][0] = bv.x; acc[nt][1] = bv.y;
        acc[nt][2] = bv.x; acc[nt][3] = bv.y;
    }

    int am = lane >> 3;
    int arow = wid * 16 + (lane & 7) + (am & 1) * 8;
    int achunkoff = am >> 1;
    int brow_loc  = ((lane >> 4) << 3) + (lane & 7);
    int bchunkoff = (lane >> 3) & 1;

    uint32_t aHi = smem_base + OFF_AHI, aLo = smem_base + OFF_ALO;
    uint32_t bHi = smem_base + OFF_BHI, bLo = smem_base + OFF_BLO;

    #pragma unroll
    for (int ks = 0; ks < 8; ks++) {
        uint32_t ah[4], al[4];
        int achunk = ks * 2 + achunkoff;
        uint32_t aoff = (uint32_t)arow * 256u + (uint32_t)((achunk ^ (arow & 7)) << 4);
        ldsm4(ah, aHi + aoff);
        ldsm4(al, aLo + aoff);
        #pragma unroll
        for (int np = 0; np < 8; np++) {
            int brow = np * 16 + brow_loc;
            int bchunk = ks * 2 + bchunkoff;
            uint32_t boff = (uint32_t)brow * 256u + (uint32_t)((bchunk ^ (brow & 7)) << 4);
            uint32_t bh[4], bl[4];
            ldsm4(bh, bHi + boff);
            ldsm4(bl, bLo + boff);
            mma_bf16(acc[2 * np + 0], ah, bh + 0);
            mma_bf16(acc[2 * np + 1], ah, bh + 2);
            mma_bf16(acc[2 * np + 0], ah, bl + 0);
            mma_bf16(acc[2 * np + 1], ah, bl + 2);
            mma_bf16(acc[2 * np + 0], al, bh + 0);
            mma_bf16(acc[2 * np + 1], al, bh + 2);
        }
    }

    int r0 = row0 + wid * 16 + (lane >> 2);
    int r1 = r0 + 8;
    int cb = (lane & 3) * 2;
    #pragma unroll
    for (int nt = 0; nt < 16; nt++) {
        float2 v0 = make_float2(acc[nt][0], acc[nt][1]);
        float2 v1 = make_float2(acc[nt][2], acc[nt][3]);
        if (RELU) {
            v0.x = fmaxf(v0.x, 0.f); v0.y = fmaxf(v0.y, 0.f);
            v1.x = fmaxf(v1.x, 0.f); v1.y = fmaxf(v1.y, 0.f);
        }
        if (r0 < N_NODES) *(float2*)(C + (size_t)r0 * D + nt * 8 + cb) = v0;
        if (r1 < N_NODES) *(float2*)(C + (size_t)r1 * D + nt * 8 + cb) = v1;
    }
}

// ---------------------------------------------------------------------------
static bool g_attr_done = false;

extern "C" void kernel_launch(void* const* d_in, const int* in_sizes, int n_in,
                              void* d_out, int out_size)
{
    const float* x     = (const float*)d_in[0];
    const void*  eidx  =               d_in[1];
    const float* ea    = (const float*)d_in[2];
    const float* w1_0  = (const float*)d_in[3];
    const float* b1_0  = (const float*)d_in[4];
    const float* w2_0  = (const float*)d_in[5];
    const float* b2_0  = (const float*)d_in[6];
    const float* we_0  = (const float*)d_in[7];
    const float* be_0  = (const float*)d_in[8];
    const float* w1_1  = (const float*)d_in[9];
    const float* b1_1  = (const float*)d_in[10];
    const float* w2_1  = (const float*)d_in[11];
    const float* b2_1  = (const float*)d_in[12];
    const float* we_1  = (const float*)d_in[13];
    const float* be_1  = (const float*)d_in[14];
    const float* fc1_w = (const float*)d_in[15];
    const float* fc1_b = (const float*)d_in[16];
    const float* fc2_w = (const float*)d_in[17];
    const float* fc2_b = (const float*)d_in[18];
    float* out = (float*)d_out;

    float *bufA, *bufB, *bufC;
    __nv_bfloat16 *whi, *wlo, *wehi, *welo;
    cudaGetSymbolAddress((void**)&bufA, g_bufA);
    cudaGetSymbolAddress((void**)&bufB, g_bufB);
    cudaGetSymbolAddress((void**)&bufC, g_bufC);
    cudaGetSymbolAddress((void**)&whi,  g_whi);
    cudaGetSymbolAddress((void**)&wlo,  g_wlo);
    cudaGetSymbolAddress((void**)&wehi, g_wehi);
    cudaGetSymbolAddress((void**)&welo, g_welo);

    if (!g_attr_done) {
        cudaFuncSetAttribute((const void*)gemm_mma<true>,
                             cudaFuncAttributeMaxDynamicSharedMemorySize, SMEM_MMA);
        cudaFuncSetAttribute((const void*)gemm_mma<false>,
                             cudaFuncAttributeMaxDynamicSharedMemorySize, SMEM_MMA);
        cudaFuncSetAttribute((const void*)edge_mma,
                             cudaFuncAttributeMaxDynamicSharedMemorySize, SMEM_EDGE);
        g_attr_done = true;
    }

    int n_words = in_sizes[1];
    detect_kernel<<<1, 32>>>((const int*)eidx, n_words);
    convert_kernel<<<(N_EDGES + 255) / 256, 256>>>(eidx);

    // pre-split weights into operand layouts
    const float* Ws[6] = {w1_0, w2_0, w1_1, w2_1, fc1_w, fc2_w};
    for (int i = 0; i < 6; i++)
        wsplit_kernel<<<64, 256>>>(Ws[i], whi + i * D * D, wlo + i * D * D);
    wesplit_kernel<<<16, 256>>>(we_0, wehi + 0 * 5120, welo + 0 * 5120);
    wesplit_kernel<<<16, 256>>>(we_1, wehi + 1 * 5120, welo + 1 * 5120);

    int n4 = N_NODES * D / 4;
    int gt = (N_NODES + 127) / 128;     // 391 node M-tiles
    int ge = (N_EDGES + 127) / 128;     // 4688 edge tiles

    // ----- layer 0 -----
    copy_kernel<<<(n4 + 255) / 256, 256>>>((const float4*)x, (float4*)bufA, n4);
    edge_mma<<<ge, 256, SMEM_EDGE>>>(x, ea, wehi + 0 * 5120, welo + 0 * 5120, be_0, bufA);
    gemm_mma<true ><<<gt, 256, SMEM_MMA>>>(bufA, whi + 0 * D * D, wlo + 0 * D * D, b1_0, bufB);
    gemm_mma<true ><<<gt, 256, SMEM_MMA>>>(bufB, whi + 1 * D * D, wlo + 1 * D * D, b2_0, bufC);

    // ----- layer 1 -----
    copy_kernel<<<(n4 + 255) / 256, 256>>>((const float4*)bufC, (float4*)bufA, n4);
    edge_mma<<<ge, 256, SMEM_EDGE>>>(bufC, ea, wehi + 1 * 5120, welo + 1 * 5120, be_1, bufA);
    gemm_mma<true ><<<gt, 256, SMEM_MMA>>>(bufA, whi + 2 * D * D, wlo + 2 * D * D, b1_1, bufB);
    gemm_mma<true ><<<gt, 256, SMEM_MMA>>>(bufB, whi + 3 * D * D, wlo + 3 * D * D, b2_1, bufC);

    // ----- head -----
    gemm_mma<true ><<<gt, 256, SMEM_MMA>>>(bufC, whi + 4 * D * D, wlo + 4 * D * D, fc1_b, bufB);
    gemm_mma<false><<<gt, 256, SMEM_MMA>>>(bufB, whi + 5 * D * D, wlo + 5 * D * D, fc2_b, out);
}

// round 10
// speedup vs baseline: 1.6033x; 1.6033x over previous
#include <cuda_runtime.h>
#include <cuda_bf16.h>
#include <cstdint>

#define N_NODES 50000
#define N_EDGES 600000
#define D 128
#define DE 32

// ---------------------------------------------------------------------------
// Scratch (static device globals — no runtime allocation allowed)
// ---------------------------------------------------------------------------
__device__ int   g_src[N_EDGES];
__device__ int   g_dst[N_EDGES];
__device__ float g_bufA[N_NODES * D];
__device__ float g_bufB[N_NODES * D];
__device__ float g_bufC[N_NODES * D];
__device__ int   g_is64;
// node-GEMM weights: [6][128x128 bf16] in B-operand layout (stride 256B, XOR swizzle)
__device__ __nv_bfloat16 g_whi[6][D * D];
__device__ __nv_bfloat16 g_wlo[6][D * D];

// ---------------------------------------------------------------------------
// helpers
// ---------------------------------------------------------------------------
__device__ __forceinline__ uint32_t smem_to_u32(const void* p) {
    uint32_t a;
    asm("{ .reg .u64 t; cvta.to.shared.u64 t, %1; cvt.u32.u64 %0, t; }" : "=r"(a) : "l"(p));
    return a;
}

// node-GEMM plane: [128 rows x 128 cols] bf16, row stride 256B, 16B chunks
// XOR-swizzled by (row & 7)
__device__ __host__ __forceinline__ uint32_t sw_off(int row, int col) {
    return (uint32_t)row * 256u + (uint32_t)(((col >> 3) ^ (row & 7)) << 4)
         + (uint32_t)(col & 7) * 2u;
}

__device__ __forceinline__ void ldsm4(uint32_t* r, uint32_t addr) {
    asm volatile("ldmatrix.sync.aligned.m8n8.x4.shared.b16 {%0,%1,%2,%3}, [%4];"
                 : "=r"(r[0]), "=r"(r[1]), "=r"(r[2]), "=r"(r[3]) : "r"(addr));
}

__device__ __forceinline__ void mma_bf16(float* d, const uint32_t* a, const uint32_t* b) {
    asm volatile("mma.sync.aligned.m16n8k16.row.col.f32.bf16.bf16.f32 "
                 "{%0,%1,%2,%3}, {%4,%5,%6,%7}, {%8,%9}, {%0,%1,%2,%3};"
                 : "+f"(d[0]), "+f"(d[1]), "+f"(d[2]), "+f"(d[3])
                 : "r"(a[0]), "r"(a[1]), "r"(a[2]), "r"(a[3]), "r"(b[0]), "r"(b[1]));
}

__device__ __forceinline__ void split_pack(float4 v, uint2& hi, uint2& lo) {
    __nv_bfloat16 hx = __float2bfloat16(v.x), hy = __float2bfloat16(v.y);
    __nv_bfloat16 hz = __float2bfloat16(v.z), hw = __float2bfloat16(v.w);
    __nv_bfloat16 lx = __float2bfloat16(v.x - __bfloat162float(hx));
    __nv_bfloat16 ly = __float2bfloat16(v.y - __bfloat162float(hy));
    __nv_bfloat16 lz = __float2bfloat16(v.z - __bfloat162float(hz));
    __nv_bfloat16 lw = __float2bfloat16(v.w - __bfloat162float(hw));
    hi.x = ((uint32_t)__bfloat16_as_ushort(hy) << 16) | __bfloat16_as_ushort(hx);
    hi.y = ((uint32_t)__bfloat16_as_ushort(hw) << 16) | __bfloat16_as_ushort(hz);
    lo.x = ((uint32_t)__bfloat16_as_ushort(ly) << 16) | __bfloat16_as_ushort(lx);
    lo.y = ((uint32_t)__bfloat16_as_ushort(lw) << 16) | __bfloat16_as_ushort(lz);
}

// ---------------------------------------------------------------------------
// edge_index dtype detection / conversion / copy
// ---------------------------------------------------------------------------
__global__ void detect_kernel(const int* __restrict__ p, int n_words) {
    if (threadIdx.x == 0 && blockIdx.x == 0) {
        int all0 = 1;
        int lim = n_words / 2 < 64 ? n_words / 2 : 64;
        for (int i = 0; i < lim; i++) {
            if (p[2 * i + 1] != 0) { all0 = 0; break; }
        }
        g_is64 = all0;
    }
}

__global__ void convert_kernel(const void* __restrict__ eidx) {
    int e = blockIdx.x * blockDim.x + threadIdx.x;
    if (e >= N_EDGES) return;
    if (g_is64) {
        const long long* p = (const long long*)eidx;
        g_src[e] = (int)p[e];
        g_dst[e] = (int)p[N_EDGES + e];
    } else {
        const int* p = (const int*)eidx;
        g_src[e] = p[e];
        g_dst[e] = p[N_EDGES + e];
    }
}

__global__ void copy_kernel(const float4* __restrict__ src, float4* __restrict__ dst, int n4) {
    int i = blockIdx.x * blockDim.x + threadIdx.x;
    if (i < n4) dst[i] = src[i];
}

// ---------------------------------------------------------------------------
// Weight pre-split for node GEMMs
// ---------------------------------------------------------------------------
__global__ void wsplit_kernel(const float* __restrict__ W,
                              __nv_bfloat16* __restrict__ whi,
                              __nv_bfloat16* __restrict__ wlo) {
    int idx = blockIdx.x * blockDim.x + threadIdx.x;
    if (idx >= D * D) return;
    int n = idx >> 7;
    int k = idx & 127;
    float w = W[k * D + n];
    __nv_bfloat16 hi = __float2bfloat16(w);
    __nv_bfloat16 lo = __float2bfloat16(w - __bfloat162float(hi));
    uint32_t off = sw_off(n, k);
    *(__nv_bfloat16*)((char*)whi + off) = hi;
    *(__nv_bfloat16*)((char*)wlo + off) = lo;
}

// ---------------------------------------------------------------------------
// Scalar edge kernel (R5 winner) + MLP-restructured tail:
// all 8 src/dst loads, then all 8 gathers, then compute+red.
// ---------------------------------------------------------------------------
__global__ void __launch_bounds__(256, 2) edge_kernel(
    const float* __restrict__ X, const float* __restrict__ ea,
    const float* __restrict__ we, const float* __restrict__ be,
    float* __restrict__ agg)
{
    __shared__ float  s_we[DE * D];
    __shared__ float4 s_ea[8][8][8];

    int tid  = threadIdx.x;
    int lane = tid & 31;
    int w    = tid >> 5;

    for (int i = tid; i < DE * D / 4; i += 256)
        ((float4*)s_we)[i] = ((const float4*)we)[i];
    __syncthreads();

    const float4* s_we4 = (const float4*)s_we;
    float4 bias = ((const float4*)be)[lane];

    int gw     = blockIdx.x * 8 + w;
    int nwarp  = gridDim.x * 8;
    int nbatch = N_EDGES / 8;

    for (int batch = gw; batch < nbatch; batch += nwarp) {
        int e0 = batch * 8;

        float4* sw = &s_ea[w][0][0];
        #pragma unroll
        for (int p = 0; p < 2; p++) {
            int idx = p * 32 + lane;
            sw[idx] = ((const float4*)ea)[(size_t)e0 * 8 + idx];
        }
        __syncwarp();

        float4 acc[8];
        #pragma unroll
        for (int i = 0; i < 8; i++) acc[i] = bias;

        #pragma unroll
        for (int k4 = 0; k4 < 8; k4++) {
            float4 wv0 = s_we4[(k4 * 4 + 0) * 32 + lane];
            float4 wv1 = s_we4[(k4 * 4 + 1) * 32 + lane];
            float4 wv2 = s_we4[(k4 * 4 + 2) * 32 + lane];
            float4 wv3 = s_we4[(k4 * 4 + 3) * 32 + lane];
            #pragma unroll
            for (int i = 0; i < 8; i++) {
                float4 a = s_ea[w][i][k4];
                acc[i].x = fmaf(a.x, wv0.x, acc[i].x);
                acc[i].y = fmaf(a.x, wv0.y, acc[i].y);
                acc[i].z = fmaf(a.x, wv0.z, acc[i].z);
                acc[i].w = fmaf(a.x, wv0.w, acc[i].w);
                acc[i].x = fmaf(a.y, wv1.x, acc[i].x);
                acc[i].y = fmaf(a.y, wv1.y, acc[i].y);
                acc[i].z = fmaf(a.y, wv1.z, acc[i].z);
                acc[i].w = fmaf(a.y, wv1.w, acc[i].w);
                acc[i].x = fmaf(a.z, wv2.x, acc[i].x);
                acc[i].y = fmaf(a.z, wv2.y, acc[i].y);
                acc[i].z = fmaf(a.z, wv2.z, acc[i].z);
                acc[i].w = fmaf(a.z, wv2.w, acc[i].w);
                acc[i].x = fmaf(a.w, wv3.x, acc[i].x);
                acc[i].y = fmaf(a.w, wv3.y, acc[i].y);
                acc[i].z = fmaf(a.w, wv3.z, acc[i].z);
                acc[i].w = fmaf(a.w, wv3.w, acc[i].w);
            }
        }

        // tail: prefetch indices, then all gathers (MLP=8), then compute+red
        int srcs[8], dsts[8];
        #pragma unroll
        for (int i = 0; i < 8; i++) { srcs[i] = g_src[e0 + i]; dsts[i] = g_dst[e0 + i]; }
        float4 xv[8];
        #pragma unroll
        for (int i = 0; i < 8; i++)
            xv[i] = ((const float4*)X)[(size_t)srcs[i] * 32 + lane];
        #pragma unroll
        for (int i = 0; i < 8; i++) {
            float mx = fmaxf(acc[i].x + xv[i].x, 0.f);
            float my = fmaxf(acc[i].y + xv[i].y, 0.f);
            float mz = fmaxf(acc[i].z + xv[i].z, 0.f);
            float mw = fmaxf(acc[i].w + xv[i].w, 0.f);
            float* p = agg + (size_t)dsts[i] * D + lane * 4;
            asm volatile("red.global.add.v4.f32 [%0], {%1,%2,%3,%4};"
                         :: "l"(p), "f"(mx), "f"(my), "f"(mz), "f"(mw) : "memory");
        }
        __syncwarp();
    }
}

// ---------------------------------------------------------------------------
// HMMA node GEMM (R7) + optional duplicate-output epilogue (folds copy_kernel)
// ---------------------------------------------------------------------------
static constexpr int OFF_AHI = 0;
static constexpr int OFF_ALO = 32768;
static constexpr int OFF_BHI = 2 * 32768;
static constexpr int OFF_BLO = 3 * 32768;
static constexpr int SMEM_MMA = 4 * 32768;   // 128 KB

template<bool RELU>
__global__ void __launch_bounds__(256) gemm_mma(
    const float* __restrict__ A,
    const __nv_bfloat16* __restrict__ Whi, const __nv_bfloat16* __restrict__ Wlo,
    const float* __restrict__ b, float* __restrict__ C, float* __restrict__ C2)
{
    extern __shared__ char sm[];
    uint32_t smem_base = smem_to_u32(sm);
    int tid  = threadIdx.x;
    int lane = tid & 31;
    int wid  = tid >> 5;

    {
        const uint4* hg = (const uint4*)Whi;
        const uint4* lg = (const uint4*)Wlo;
        uint4* hs = (uint4*)(sm + OFF_BHI);
        uint4* ls = (uint4*)(sm + OFF_BLO);
        #pragma unroll
        for (int i = 0; i < 8; i++) {
            hs[tid + i * 256] = hg[tid + i * 256];
            ls[tid + i * 256] = lg[tid + i * 256];
        }
    }

    int row0 = blockIdx.x * 128;
    #pragma unroll
    for (int i = 0; i < 16; i++) {
        int idx = tid + i * 256;
        int row = idx >> 5;
        int c4  = idx & 31;
        int rg  = row0 + row;
        if (rg >= N_NODES) rg = N_NODES - 1;
        float4 v = ((const float4*)A)[(size_t)rg * 32 + c4];
        uint2 hi, lo;
        split_pack(v, hi, lo);
        uint32_t off = sw_off(row, c4 * 4);
        *(uint2*)(sm + OFF_AHI + off) = hi;
        *(uint2*)(sm + OFF_ALO + off) = lo;
    }
    __syncthreads();

    float acc[16][4];
    #pragma unroll
    for (int nt = 0; nt < 16; nt++) {
        float2 bv = *(const float2*)(b + nt * 8 + (lane & 3) * 2);
        acc[nt][0] = bv.x; acc[nt][1] = bv.y;
        acc[nt][2] = bv.x; acc[nt][3] = bv.y;
    }

    int am = lane >> 3;
    int arow = wid * 16 + (lane & 7) + (am & 1) * 8;
    int achunkoff = am >> 1;
    int brow_loc  = ((lane >> 4) << 3) + (lane & 7);
    int bchunkoff = (lane >> 3) & 1;

    uint32_t aHi = smem_base + OFF_AHI, aLo = smem_base + OFF_ALO;
    uint32_t bHi = smem_base + OFF_BHI, bLo = smem_base + OFF_BLO;

    #pragma unroll
    for (int ks = 0; ks < 8; ks++) {
        uint32_t ah[4], al[4];
        int achunk = ks * 2 + achunkoff;
        uint32_t aoff = (uint32_t)arow * 256u + (uint32_t)((achunk ^ (arow & 7)) << 4);
        ldsm4(ah, aHi + aoff);
        ldsm4(al, aLo + aoff);
        #pragma unroll
        for (int np = 0; np < 8; np++) {
            int brow = np * 16 + brow_loc;
            int bchunk = ks * 2 + bchunkoff;
            uint32_t boff = (uint32_t)brow * 256u + (uint32_t)((bchunk ^ (brow & 7)) << 4);
            uint32_t bh[4], bl[4];
            ldsm4(bh, bHi + boff);
            ldsm4(bl, bLo + boff);
            mma_bf16(acc[2 * np + 0], ah, bh + 0);
            mma_bf16(acc[2 * np + 1], ah, bh + 2);
            mma_bf16(acc[2 * np + 0], ah, bl + 0);
            mma_bf16(acc[2 * np + 1], ah, bl + 2);
            mma_bf16(acc[2 * np + 0], al, bh + 0);
            mma_bf16(acc[2 * np + 1], al, bh + 2);
        }
    }

    int r0 = row0 + wid * 16 + (lane >> 2);
    int r1 = r0 + 8;
    int cb = (lane & 3) * 2;
    #pragma unroll
    for (int nt = 0; nt < 16; nt++) {
        float2 v0 = make_float2(acc[nt][0], acc[nt][1]);
        float2 v1 = make_float2(acc[nt][2], acc[nt][3]);
        if (RELU) {
            v0.x = fmaxf(v0.x, 0.f); v0.y = fmaxf(v0.y, 0.f);
            v1.x = fmaxf(v1.x, 0.f); v1.y = fmaxf(v1.y, 0.f);
        }
        if (r0 < N_NODES) {
            *(float2*)(C + (size_t)r0 * D + nt * 8 + cb) = v0;
            if (C2) *(float2*)(C2 + (size_t)r0 * D + nt * 8 + cb) = v0;
        }
        if (r1 < N_NODES) {
            *(float2*)(C + (size_t)r1 * D + nt * 8 + cb) = v1;
            if (C2) *(float2*)(C2 + (size_t)r1 * D + nt * 8 + cb) = v1;
        }
    }
}

// ---------------------------------------------------------------------------
static bool g_attr_done = false;

extern "C" void kernel_launch(void* const* d_in, const int* in_sizes, int n_in,
                              void* d_out, int out_size)
{
    const float* x     = (const float*)d_in[0];
    const void*  eidx  =               d_in[1];
    const float* ea    = (const float*)d_in[2];
    const float* w1_0  = (const float*)d_in[3];
    const float* b1_0  = (const float*)d_in[4];
    const float* w2_0  = (const float*)d_in[5];
    const float* b2_0  = (const float*)d_in[6];
    const float* we_0  = (const float*)d_in[7];
    const float* be_0  = (const float*)d_in[8];
    const float* w1_1  = (const float*)d_in[9];
    const float* b1_1  = (const float*)d_in[10];
    const float* w2_1  = (const float*)d_in[11];
    const float* b2_1  = (const float*)d_in[12];
    const float* we_1  = (const float*)d_in[13];
    const float* be_1  = (const float*)d_in[14];
    const float* fc1_w = (const float*)d_in[15];
    const float* fc1_b = (const float*)d_in[16];
    const float* fc2_w = (const float*)d_in[17];
    const float* fc2_b = (const float*)d_in[18];
    float* out = (float*)d_out;

    float *bufA, *bufB, *bufC;
    __nv_bfloat16 *whi, *wlo;
    cudaGetSymbolAddress((void**)&bufA, g_bufA);
    cudaGetSymbolAddress((void**)&bufB, g_bufB);
    cudaGetSymbolAddress((void**)&bufC, g_bufC);
    cudaGetSymbolAddress((void**)&whi,  g_whi);
    cudaGetSymbolAddress((void**)&wlo,  g_wlo);

    if (!g_attr_done) {
        cudaFuncSetAttribute((const void*)gemm_mma<true>,
                             cudaFuncAttributeMaxDynamicSharedMemorySize, SMEM_MMA);
        cudaFuncSetAttribute((const void*)gemm_mma<false>,
                             cudaFuncAttributeMaxDynamicSharedMemorySize, SMEM_MMA);
        g_attr_done = true;
    }

    int n_words = in_sizes[1];
    detect_kernel<<<1, 32>>>((const int*)eidx, n_words);
    convert_kernel<<<(N_EDGES + 255) / 256, 256>>>(eidx);

    // pre-split the 6 node-GEMM weights into B-operand layout
    const float* Ws[6] = {w1_0, w2_0, w1_1, w2_1, fc1_w, fc2_w};
    for (int i = 0; i < 6; i++)
        wsplit_kernel<<<64, 256>>>(Ws[i], whi + i * D * D, wlo + i * D * D);

    int n4 = N_NODES * D / 4;
    int gt = (N_NODES + 127) / 128;   // 391 M-tiles

    // ----- layer 0 -----
    copy_kernel<<<(n4 + 255) / 256, 256>>>((const float4*)x, (float4*)bufA, n4);
    edge_kernel<<<1184, 256>>>(x, ea, we_0, be_0, bufA);
    gemm_mma<true ><<<gt, 256, SMEM_MMA>>>(bufA, whi + 0 * D * D, wlo + 0 * D * D, b1_0, bufB, nullptr);
    // last gemm of layer 0 also initializes layer-1's agg buffer (dup store)
    gemm_mma<true ><<<gt, 256, SMEM_MMA>>>(bufB, whi + 1 * D * D, wlo + 1 * D * D, b2_0, bufC, bufA);

    // ----- layer 1 -----
    edge_kernel<<<1184, 256>>>(bufC, ea, we_1, be_1, bufA);
    gemm_mma<true ><<<gt, 256, SMEM_MMA>>>(bufA, whi + 2 * D * D, wlo + 2 * D * D, b1_1, bufB, nullptr);
    gemm_mma<true ><<<gt, 256, SMEM_MMA>>>(bufB, whi + 3 * D * D, wlo + 3 * D * D, b2_1, bufC, nullptr);

    // ----- head -----
    gemm_mma<true ><<<gt, 256, SMEM_MMA>>>(bufC, whi + 4 * D * D, wlo + 4 * D * D, fc1_b, bufB, nullptr);
    gemm_mma<false><<<gt, 256, SMEM_MMA>>>(bufB, whi + 5 * D * D, wlo + 5 * D * D, fc2_b, out, nullptr);
}

// round 11
// speedup vs baseline: 1.7854x; 1.1136x over previous
#include <cuda_runtime.h>
#include <cuda_bf16.h>
#include <cstdint>

#define N_NODES 50000
#define N_EDGES 600000
#define D 128
#define DE 32

// ---------------------------------------------------------------------------
// Scratch (static device globals — no runtime allocation allowed)
// ---------------------------------------------------------------------------
__device__ int   g_src[N_EDGES];
__device__ int   g_dst[N_EDGES];
__device__ float g_bufA[N_NODES * D];
__device__ float g_bufB[N_NODES * D];
__device__ float g_bufC[N_NODES * D];
__device__ int   g_is64;
// node-GEMM weights: [6][128x128 bf16] in B-operand layout (stride 256B, XOR swizzle)
__device__ __nv_bfloat16 g_whi[6][D * D];
__device__ __nv_bfloat16 g_wlo[6][D * D];
// edge weights: [2 layers][128 n-rows x 80B stride] hi/lo planes (5120 bf16 each)
__device__ __nv_bfloat16 g_wehi[2][5120];
__device__ __nv_bfloat16 g_welo[2][5120];

// ---------------------------------------------------------------------------
// helpers
// ---------------------------------------------------------------------------
__device__ __forceinline__ uint32_t smem_to_u32(const void* p) {
    uint32_t a;
    asm("{ .reg .u64 t; cvta.to.shared.u64 t, %1; cvt.u32.u64 %0, t; }" : "=r"(a) : "l"(p));
    return a;
}

// node-GEMM plane: [128 rows x 128 cols] bf16, row stride 256B, 16B chunks
// XOR-swizzled by (row & 7)
__device__ __host__ __forceinline__ uint32_t sw_off(int row, int col) {
    return (uint32_t)row * 256u + (uint32_t)(((col >> 3) ^ (row & 7)) << 4)
         + (uint32_t)(col & 7) * 2u;
}
// edge plane: [rows x 32 cols] bf16, row stride 80B (8 consecutive rows hit
// distinct 16B banks -> ldmatrix conflict-free, no XOR needed)
__device__ __host__ __forceinline__ uint32_t esw_off(int row, int col) {
    return (uint32_t)row * 80u + (uint32_t)((col >> 3) << 4) + (uint32_t)(col & 7) * 2u;
}

__device__ __forceinline__ void ldsm4(uint32_t* r, uint32_t addr) {
    asm volatile("ldmatrix.sync.aligned.m8n8.x4.shared.b16 {%0,%1,%2,%3}, [%4];"
                 : "=r"(r[0]), "=r"(r[1]), "=r"(r[2]), "=r"(r[3]) : "r"(addr));
}

__device__ __forceinline__ void mma_bf16(float* d, const uint32_t* a, const uint32_t* b) {
    asm volatile("mma.sync.aligned.m16n8k16.row.col.f32.bf16.bf16.f32 "
                 "{%0,%1,%2,%3}, {%4,%5,%6,%7}, {%8,%9}, {%0,%1,%2,%3};"
                 : "+f"(d[0]), "+f"(d[1]), "+f"(d[2]), "+f"(d[3])
                 : "r"(a[0]), "r"(a[1]), "r"(a[2]), "r"(a[3]), "r"(b[0]), "r"(b[1]));
}

__device__ __forceinline__ void split_pack(float4 v, uint2& hi, uint2& lo) {
    __nv_bfloat16 hx = __float2bfloat16(v.x), hy = __float2bfloat16(v.y);
    __nv_bfloat16 hz = __float2bfloat16(v.z), hw = __float2bfloat16(v.w);
    __nv_bfloat16 lx = __float2bfloat16(v.x - __bfloat162float(hx));
    __nv_bfloat16 ly = __float2bfloat16(v.y - __bfloat162float(hy));
    __nv_bfloat16 lz = __float2bfloat16(v.z - __bfloat162float(hz));
    __nv_bfloat16 lw = __float2bfloat16(v.w - __bfloat162float(hw));
    hi.x = ((uint32_t)__bfloat16_as_ushort(hy) << 16) | __bfloat16_as_ushort(hx);
    hi.y = ((uint32_t)__bfloat16_as_ushort(hw) << 16) | __bfloat16_as_ushort(hz);
    lo.x = ((uint32_t)__bfloat16_as_ushort(ly) << 16) | __bfloat16_as_ushort(lx);
    lo.y = ((uint32_t)__bfloat16_as_ushort(lw) << 16) | __bfloat16_as_ushort(lz);
}

// ---------------------------------------------------------------------------
// edge_index dtype detection / conversion / copy
// ---------------------------------------------------------------------------
__global__ void detect_kernel(const int* __restrict__ p, int n_words) {
    if (threadIdx.x == 0 && blockIdx.x == 0) {
        int all0 = 1;
        int lim = n_words / 2 < 64 ? n_words / 2 : 64;
        for (int i = 0; i < lim; i++) {
            if (p[2 * i + 1] != 0) { all0 = 0; break; }
        }
        g_is64 = all0;
    }
}

__global__ void convert_kernel(const void* __restrict__ eidx) {
    int e = blockIdx.x * blockDim.x + threadIdx.x;
    if (e >= N_EDGES) return;
    if (g_is64) {
        const long long* p = (const long long*)eidx;
        g_src[e] = (int)p[e];
        g_dst[e] = (int)p[N_EDGES + e];
    } else {
        const int* p = (const int*)eidx;
        g_src[e] = p[e];
        g_dst[e] = p[N_EDGES + e];
    }
}

__global__ void copy_kernel(const float4* __restrict__ src, float4* __restrict__ dst, int n4) {
    int i = blockIdx.x * blockDim.x + threadIdx.x;
    if (i < n4) dst[i] = src[i];
}

// ---------------------------------------------------------------------------
// Weight pre-splits
// ---------------------------------------------------------------------------
__global__ void wsplit_kernel(const float* __restrict__ W,
                              __nv_bfloat16* __restrict__ whi,
                              __nv_bfloat16* __restrict__ wlo) {
    int idx = blockIdx.x * blockDim.x + threadIdx.x;
    if (idx >= D * D) return;
    int n = idx >> 7;
    int k = idx & 127;
    float w = W[k * D + n];
    __nv_bfloat16 hi = __float2bfloat16(w);
    __nv_bfloat16 lo = __float2bfloat16(w - __bfloat162float(hi));
    uint32_t off = sw_off(n, k);
    *(__nv_bfloat16*)((char*)whi + off) = hi;
    *(__nv_bfloat16*)((char*)wlo + off) = lo;
}

// we[32][128] -> B-operand edge layout: row n (0..127), col k (0..31)
__global__ void wesplit_kernel(const float* __restrict__ we,
                               __nv_bfloat16* __restrict__ whi,
                               __nv_bfloat16* __restrict__ wlo) {
    int idx = blockIdx.x * blockDim.x + threadIdx.x;   // 4096
    if (idx >= DE * D) return;
    int n = idx & 127;
    int k = idx >> 7;
    float w = we[k * D + n];
    __nv_bfloat16 hi = __float2bfloat16(w);
    __nv_bfloat16 lo = __float2bfloat16(w - __bfloat162float(hi));
    uint32_t off = esw_off(n, k);
    *(__nv_bfloat16*)((char*)whi + off) = hi;
    *(__nv_bfloat16*)((char*)wlo + off) = lo;
}

// ---------------------------------------------------------------------------
// Warp-autonomous HMMA edge kernel: each warp owns private 16-edge tiles.
//   emb[16,128] = ea_tile[16,32] @ we[32,128] + be   (bf16 hi/lo, 3 terms)
//   msg = relu(emb + X[src]);  agg[dst] += msg
// Only __syncwarp inside the loop -> warps free-run like the scalar version,
// but the arithmetic rides the tensor pipe.
// smem: we hi/lo (2x10240) + per-warp A hi/lo (8x2560) + per-warp emb (8x8448)
// ---------------------------------------------------------------------------
static constexpr int EOFF_WB   = 0;            // we hi (10240) + lo (10240)
static constexpr int EOFF_AST  = 20480;        // per-warp A staging: w*2560 (hi 1280, lo 1280)
static constexpr int EOFF_EMB  = 40960;        // per-warp emb: w*8448 (16 rows x 132 floats)
static constexpr int EMB_STRIDE = 132;
static constexpr int SMEM_EDGE = 40960 + 8 * 8448;   // 108544

__global__ void __launch_bounds__(256, 2) edge_mma(
    const float* __restrict__ X, const float* __restrict__ ea,
    const __nv_bfloat16* __restrict__ wehi, const __nv_bfloat16* __restrict__ welo,
    const float* __restrict__ be, float* __restrict__ agg)
{
    extern __shared__ char sm[];
    uint32_t smem_base = smem_to_u32(sm);
    int tid  = threadIdx.x;
    int lane = tid & 31;
    int wid  = tid >> 5;

    // stage we planes once per CTA (hi then lo, contiguous): 1280 uint4
    {
        const uint4* hg = (const uint4*)wehi;
        const uint4* lg = (const uint4*)welo;
        uint4* s = (uint4*)(sm + EOFF_WB);
        for (int i = tid; i < 640; i += 256) { s[i] = hg[i]; s[640 + i] = lg[i]; }
    }
    __syncthreads();

    // per-warp bases
    uint32_t aHi = smem_base + EOFF_AST + wid * 2560;
    uint32_t aLo = aHi + 1280;
    uint32_t bHi = smem_base + EOFF_WB;
    uint32_t bLo = bHi + 10240;
    float*  embp = (float*)(sm + EOFF_EMB + wid * 8448);

    // frag index mappings (validated in R7/R8)
    int am = lane >> 3;
    int arow = (lane & 7) + (am & 1) * 8;
    int achunkoff = am >> 1;
    int brow_loc  = ((lane >> 4) << 3) + (lane & 7);
    int bchunkoff = (lane >> 3) & 1;

    int gw     = blockIdx.x * 8 + wid;
    int nwarp  = gridDim.x * 8;
    int ntile  = N_EDGES / 16;          // 37500, exact

    for (int t = gw; t < ntile; t += nwarp) {
        int e0 = t * 16;

        // stage 16 edges x 32 attrs = 128 float4; 4 per lane, split hi/lo
        #pragma unroll
        for (int p = 0; p < 4; p++) {
            int idx = p * 32 + lane;
            int row = idx >> 3;
            int c4  = idx & 7;
            float4 v = ((const float4*)ea)[(size_t)(e0 + row) * 8 + c4];
            uint2 hi, lo;
            split_pack(v, hi, lo);
            uint32_t off = (uint32_t)row * 80u + (uint32_t)(c4 >> 1) * 16u
                         + (uint32_t)(c4 & 1) * 8u;
            *(uint2*)(sm + (aHi - smem_base) + off) = hi;
            *(uint2*)(sm + (aLo - smem_base) + off) = lo;
        }
        __syncwarp();

        // accumulators with bias folded in
        float acc[16][4];
        #pragma unroll
        for (int nt = 0; nt < 16; nt++) {
            float2 bv = *(const float2*)(be + nt * 8 + (lane & 3) * 2);
            acc[nt][0] = bv.x; acc[nt][1] = bv.y;
            acc[nt][2] = bv.x; acc[nt][3] = bv.y;
        }

        #pragma unroll
        for (int ks = 0; ks < 2; ks++) {
            uint32_t ah[4], al[4];
            uint32_t aoff = (uint32_t)arow * 80u + (uint32_t)(ks * 2 + achunkoff) * 16u;
            ldsm4(ah, aHi + aoff);
            ldsm4(al, aLo + aoff);
            #pragma unroll
            for (int np = 0; np < 8; np++) {
                uint32_t boff = (uint32_t)(np * 16 + brow_loc) * 80u
                              + (uint32_t)(ks * 2 + bchunkoff) * 16u;
                uint32_t bh[4], bl[4];
                ldsm4(bh, bHi + boff);
                ldsm4(bl, bLo + boff);
                mma_bf16(acc[2 * np + 0], ah, bh + 0);
                mma_bf16(acc[2 * np + 1], ah, bh + 2);
                mma_bf16(acc[2 * np + 0], ah, bl + 0);
                mma_bf16(acc[2 * np + 1], ah, bl + 2);
                mma_bf16(acc[2 * np + 0], al, bh + 0);
                mma_bf16(acc[2 * np + 1], al, bh + 2);
            }
        }

        // frag -> per-warp emb smem (row-major, padded stride)
        {
            int r0 = lane >> 2;
            int r1 = r0 + 8;
            int cb = (lane & 3) * 2;
            #pragma unroll
            for (int nt = 0; nt < 16; nt++) {
                *(float2*)(embp + r0 * EMB_STRIDE + nt * 8 + cb) = make_float2(acc[nt][0], acc[nt][1]);
                *(float2*)(embp + r1 * EMB_STRIDE + nt * 8 + cb) = make_float2(acc[nt][2], acc[nt][3]);
            }
        }
        __syncwarp();

        // tail: two groups of 8 edges; prefetch indices, batch gathers (MLP=8), then red
        #pragma unroll
        for (int g = 0; g < 2; g++) {
            int base = g * 8;
            int srcs[8], dsts[8];
            #pragma unroll
            for (int i = 0; i < 8; i++) {
                srcs[i] = g_src[e0 + base + i];
                dsts[i] = g_dst[e0 + base + i];
            }
            float4 xv[8];
            #pragma unroll
            for (int i = 0; i < 8; i++)
                xv[i] = ((const float4*)X)[(size_t)srcs[i] * 32 + lane];
            #pragma unroll
            for (int i = 0; i < 8; i++) {
                float4 em = *(const float4*)(embp + (base + i) * EMB_STRIDE + lane * 4);
                float mx = fmaxf(em.x + xv[i].x, 0.f);
                float my = fmaxf(em.y + xv[i].y, 0.f);
                float mz = fmaxf(em.z + xv[i].z, 0.f);
                float mw = fmaxf(em.w + xv[i].w, 0.f);
                float* p = agg + (size_t)dsts[i] * D + lane * 4;
                asm volatile("red.global.add.v4.f32 [%0], {%1,%2,%3,%4};"
                             :: "l"(p), "f"(mx), "f"(my), "f"(mz), "f"(mw) : "memory");
            }
        }
        __syncwarp();
    }
}

// ---------------------------------------------------------------------------
// HMMA node GEMM (R7) + optional duplicate-output epilogue (folds copy_kernel)
// ---------------------------------------------------------------------------
static constexpr int OFF_AHI = 0;
static constexpr int OFF_ALO = 32768;
static constexpr int OFF_BHI = 2 * 32768;
static constexpr int OFF_BLO = 3 * 32768;
static constexpr int SMEM_MMA = 4 * 32768;   // 128 KB

template<bool RELU>
__global__ void __launch_bounds__(256) gemm_mma(
    const float* __restrict__ A,
    const __nv_bfloat16* __restrict__ Whi, const __nv_bfloat16* __restrict__ Wlo,
    const float* __restrict__ b, float* __restrict__ C, float* __restrict__ C2)
{
    extern __shared__ char sm[];
    uint32_t smem_base = smem_to_u32(sm);
    int tid  = threadIdx.x;
    int lane = tid & 31;
    int wid  = tid >> 5;

    {
        const uint4* hg = (const uint4*)Whi;
        const uint4* lg = (const uint4*)Wlo;
        uint4* hs = (uint4*)(sm + OFF_BHI);
        uint4* ls = (uint4*)(sm + OFF_BLO);
        #pragma unroll
        for (int i = 0; i < 8; i++) {
            hs[tid + i * 256] = hg[tid + i * 256];
            ls[tid + i * 256] = lg[tid + i * 256];
        }
    }

    int row0 = blockIdx.x * 128;
    #pragma unroll
    for (int i = 0; i < 16; i++) {
        int idx = tid + i * 256;
        int row = idx >> 5;
        int c4  = idx & 31;
        int rg  = row0 + row;
        if (rg >= N_NODES) rg = N_NODES - 1;
        float4 v = ((const float4*)A)[(size_t)rg * 32 + c4];
        uint2 hi, lo;
        split_pack(v, hi, lo);
        uint32_t off = sw_off(row, c4 * 4);
        *(uint2*)(sm + OFF_AHI + off) = hi;
        *(uint2*)(sm + OFF_ALO + off) = lo;
    }
    __syncthreads();

    float acc[16][4];
    #pragma unroll
    for (int nt = 0; nt < 16; nt++) {
        float2 bv = *(const float2*)(b + nt * 8 + (lane & 3) * 2);
        acc[nt][0] = bv.x; acc[nt][1] = bv.y;
        acc[nt][2] = bv.x; acc[nt][3] = bv.y;
    }

    int am = lane >> 3;
    int arow = wid * 16 + (lane & 7) + (am & 1) * 8;
    int achunkoff = am >> 1;
    int brow_loc  = ((lane >> 4) << 3) + (lane & 7);
    int bchunkoff = (lane >> 3) & 1;

    uint32_t aHi = smem_base + OFF_AHI, aLo = smem_base + OFF_ALO;
    uint32_t bHi = smem_base + OFF_BHI, bLo = smem_base + OFF_BLO;

    #pragma unroll
    for (int ks = 0; ks < 8; ks++) {
        uint32_t ah[4], al[4];
        int achunk = ks * 2 + achunkoff;
        uint32_t aoff = (uint32_t)arow * 256u + (uint32_t)((achunk ^ (arow & 7)) << 4);
        ldsm4(ah, aHi + aoff);
        ldsm4(al, aLo + aoff);
        #pragma unroll
        for (int np = 0; np < 8; np++) {
            int brow = np * 16 + brow_loc;
            int bchunk = ks * 2 + bchunkoff;
            uint32_t boff = (uint32_t)brow * 256u + (uint32_t)((bchunk ^ (brow & 7)) << 4);
            uint32_t bh[4], bl[4];
            ldsm4(bh, bHi + boff);
            ldsm4(bl, bLo + boff);
            mma_bf16(acc[2 * np + 0], ah, bh + 0);
            mma_bf16(acc[2 * np + 1], ah, bh + 2);
            mma_bf16(acc[2 * np + 0], ah, bl + 0);
            mma_bf16(acc[2 * np + 1], ah, bl + 2);
            mma_bf16(acc[2 * np + 0], al, bh + 0);
            mma_bf16(acc[2 * np + 1], al, bh + 2);
        }
    }

    int r0 = row0 + wid * 16 + (lane >> 2);
    int r1 = r0 + 8;
    int cb = (lane & 3) * 2;
    #pragma unroll
    for (int nt = 0; nt < 16; nt++) {
        float2 v0 = make_float2(acc[nt][0], acc[nt][1]);
        float2 v1 = make_float2(acc[nt][2], acc[nt][3]);
        if (RELU) {
            v0.x = fmaxf(v0.x, 0.f); v0.y = fmaxf(v0.y, 0.f);
            v1.x = fmaxf(v1.x, 0.f); v1.y = fmaxf(v1.y, 0.f);
        }
        if (r0 < N_NODES) {
            *(float2*)(C + (size_t)r0 * D + nt * 8 + cb) = v0;
            if (C2) *(float2*)(C2 + (size_t)r0 * D + nt * 8 + cb) = v0;
        }
        if (r1 < N_NODES) {
            *(float2*)(C + (size_t)r1 * D + nt * 8 + cb) = v1;
            if (C2) *(float2*)(C2 + (size_t)r1 * D + nt * 8 + cb) = v1;
        }
    }
}

// ---------------------------------------------------------------------------
static bool g_attr_done = false;

extern "C" void kernel_launch(void* const* d_in, const int* in_sizes, int n_in,
                              void* d_out, int out_size)
{
    const float* x     = (const float*)d_in[0];
    const void*  eidx  =               d_in[1];
    const float* ea    = (const float*)d_in[2];
    const float* w1_0  = (const float*)d_in[3];
    const float* b1_0  = (const float*)d_in[4];
    const float* w2_0  = (const float*)d_in[5];
    const float* b2_0  = (const float*)d_in[6];
    const float* we_0  = (const float*)d_in[7];
    const float* be_0  = (const float*)d_in[8];
    const float* w1_1  = (const float*)d_in[9];
    const float* b1_1  = (const float*)d_in[10];
    const float* w2_1  = (const float*)d_in[11];
    const float* b2_1  = (const float*)d_in[12];
    const float* we_1  = (const float*)d_in[13];
    const float* be_1  = (const float*)d_in[14];
    const float* fc1_w = (const float*)d_in[15];
    const float* fc1_b = (const float*)d_in[16];
    const float* fc2_w = (const float*)d_in[17];
    const float* fc2_b = (const float*)d_in[18];
    float* out = (float*)d_out;

    float *bufA, *bufB, *bufC;
    __nv_bfloat16 *whi, *wlo, *wehi, *welo;
    cudaGetSymbolAddress((void**)&bufA, g_bufA);
    cudaGetSymbolAddress((void**)&bufB, g_bufB);
    cudaGetSymbolAddress((void**)&bufC, g_bufC);
    cudaGetSymbolAddress((void**)&whi,  g_whi);
    cudaGetSymbolAddress((void**)&wlo,  g_wlo);
    cudaGetSymbolAddress((void**)&wehi, g_wehi);
    cudaGetSymbolAddress((void**)&welo, g_welo);

    if (!g_attr_done) {
        cudaFuncSetAttribute((const void*)gemm_mma<true>,
                             cudaFuncAttributeMaxDynamicSharedMemorySize, SMEM_MMA);
        cudaFuncSetAttribute((const void*)gemm_mma<false>,
                             cudaFuncAttributeMaxDynamicSharedMemorySize, SMEM_MMA);
        cudaFuncSetAttribute((const void*)edge_mma,
                             cudaFuncAttributeMaxDynamicSharedMemorySize, SMEM_EDGE);
        g_attr_done = true;
    }

    int n_words = in_sizes[1];
    detect_kernel<<<1, 32>>>((const int*)eidx, n_words);
    convert_kernel<<<(N_EDGES + 255) / 256, 256>>>(eidx);

    // pre-split weights into operand layouts
    const float* Ws[6] = {w1_0, w2_0, w1_1, w2_1, fc1_w, fc2_w};
    for (int i = 0; i < 6; i++)
        wsplit_kernel<<<64, 256>>>(Ws[i], whi + i * D * D, wlo + i * D * D);
    wesplit_kernel<<<16, 256>>>(we_0, wehi + 0 * 5120, welo + 0 * 5120);
    wesplit_kernel<<<16, 256>>>(we_1, wehi + 1 * 5120, welo + 1 * 5120);

    int n4 = N_NODES * D / 4;
    int gt = (N_NODES + 127) / 128;   // 391 M-tiles
    int ge = 296;                     // 2 CTA/SM x 148 SMs, 1 resident wave

    // ----- layer 0 -----
    copy_kernel<<<(n4 + 255) / 256, 256>>>((const float4*)x, (float4*)bufA, n4);
    edge_mma<<<ge, 256, SMEM_EDGE>>>(x, ea, wehi + 0 * 5120, welo + 0 * 5120, be_0, bufA);
    gemm_mma<true ><<<gt, 256, SMEM_MMA>>>(bufA, whi + 0 * D * D, wlo + 0 * D * D, b1_0, bufB, nullptr);
    // last gemm of layer 0 also initializes layer-1's agg buffer (dup store)
    gemm_mma<true ><<<gt, 256, SMEM_MMA>>>(bufB, whi + 1 * D * D, wlo + 1 * D * D, b2_0, bufC, bufA);

    // ----- layer 1 -----
    edge_mma<<<ge, 256, SMEM_EDGE>>>(bufC, ea, wehi + 1 * 5120, welo + 1 * 5120, be_1, bufA);
    gemm_mma<true ><<<gt, 256, SMEM_MMA>>>(bufA, whi + 2 * D * D, wlo + 2 * D * D, b1_1, bufB, nullptr);
    gemm_mma<true ><<<gt, 256, SMEM_MMA>>>(bufB, whi + 3 * D * D, wlo + 3 * D * D, b2_1, bufC, nullptr);

    // ----- head -----
    gemm_mma<true ><<<gt, 256, SMEM_MMA>>>(bufC, whi + 4 * D * D, wlo + 4 * D * D, fc1_b, bufB, nullptr);
    gemm_mma<false><<<gt, 256, SMEM_MMA>>>(bufB, whi + 5 * D * D, wlo + 5 * D * D, fc2_b, out, nullptr);
}